// round 6
// baseline (speedup 1.0000x reference)
#include <cuda_runtime.h>
#include <math.h>

// Problem constants
#define Bsz   2
#define Ssz   4096
#define Dsz   1024
#define Hn    4
#define DKn   128
#define DVn   256
#define KDn   512     // H*DK
#define VDn   1024    // H*DV
#define Csz   64
#define NCn   64      // S / C
#define RANKn 16
#define NROWS (Bsz*Ssz)   // 8192

// ---------------- scratch (device globals; no allocation allowed) -------------
__device__ float g_bufQ [NROWS*KDn];
__device__ float g_bufK [NROWS*KDn];
__device__ float g_bufV [NROWS*VDn];
__device__ float g_bufG [NROWS*VDn];
__device__ float g_bufGC[NROWS*KDn];
__device__ float g_bufT [NROWS*RANKn];
__device__ float g_bufA [Bsz*NCn*Hn*Csz*Csz];
__device__ float g_bufKV[Bsz*Hn*NCn*DKn*DVn];
__device__ float g_bufS [Bsz*Hn*NCn*DKn*DVn];
__device__ float g_bufO [NROWS*VDn];
__device__ float g_bufZ [NROWS*VDn];           // tf32-rounded at write time

// TF32 pre-converted operands
__device__ unsigned g_xC [NROWS*Dsz];          // x in tf32 bits
__device__ unsigned g_wqC[Dsz*KDn];
__device__ unsigned g_wkC[Dsz*KDn];
__device__ unsigned g_wvC[Dsz*VDn];
__device__ unsigned g_wgC[Dsz*VDn];
__device__ unsigned g_woC[VDn*Dsz];

__device__ __forceinline__ float* proj_out(int sel){
    switch(sel){
        case 0: return g_bufQ;
        case 1: return g_bufK;
        case 2: return g_bufV;
        default: return g_bufG;
    }
}

__device__ __forceinline__ unsigned f2tf32(float f){
    unsigned u;
    asm("cvt.rna.tf32.f32 %0, %1;" : "=r"(u) : "f"(f));
    return u;
}

// ---------------- elementwise fp32 -> tf32 conversion --------------------------
__global__ void cvt_tf32_kernel(const float* __restrict__ src,
                                unsigned* __restrict__ dst, int n4)
{
    int i = blockIdx.x * 256 + threadIdx.x;
    if (i < n4){
        float4 v = ((const float4*)src)[i];
        uint4 u;
        u.x = f2tf32(v.x); u.y = f2tf32(v.y); u.z = f2tf32(v.z); u.w = f2tf32(v.w);
        ((uint4*)dst)[i] = u;
    }
}

// ================= TF32 tensor-core GEMM (cp.async 3-stage) ====================
// C[M,N] = alpha * A[M,1024] @ B[1024,N]. Operands pre-converted to tf32 bits.
// Block tile 128x128, K-step 32, 256 threads = 8 warps, warp tile 64x32.

__device__ __forceinline__ void mma_tf32(float* d, const unsigned* a, const unsigned* b){
    asm volatile(
        "mma.sync.aligned.m16n8k8.row.col.f32.tf32.tf32.f32 "
        "{%0,%1,%2,%3}, {%4,%5,%6,%7}, {%8,%9}, {%0,%1,%2,%3};\n"
        : "+f"(d[0]), "+f"(d[1]), "+f"(d[2]), "+f"(d[3])
        : "r"(a[0]), "r"(a[1]), "r"(a[2]), "r"(a[3]), "r"(b[0]), "r"(b[1]));
}

__device__ __forceinline__ void cp_async16(void* smem_dst, const void* gmem_src){
    unsigned sa = (unsigned)__cvta_generic_to_shared(smem_dst);
    asm volatile("cp.async.cg.shared.global [%0], [%1], 16;\n" :: "r"(sa), "l"(gmem_src));
}
#define CP_COMMIT()  asm volatile("cp.async.commit_group;\n")
#define CP_WAIT(N)   asm volatile("cp.async.wait_group %0;\n" :: "n"(N))

// Padding: A-frag bank = (4g + r) % 32 = lane (conflict-free);
//          B-frag bank = (8r + g + c) % 32 covers all 32 (conflict-free).
#define SA_STRIDE 36
#define SB_STRIDE 136
#define SA_BUF    (128*SA_STRIDE)
#define SB_BUF    (32*SB_STRIDE)
#define NSTAGE    3
#define SMEM_WORDS (NSTAGE*(SA_BUF + SB_BUF))

__device__ __forceinline__ void tf32_load_tiles(unsigned* sA, unsigned* sB,
                                                const unsigned* __restrict__ A,
                                                const unsigned* __restrict__ Bm,
                                                int bm, int bn, int N, int k0, int buf,
                                                int tid)
{
    unsigned* a0 = sA + buf * SA_BUF;
    unsigned* b0 = sB + buf * SB_BUF;
    #pragma unroll
    for (int rep = 0; rep < 4; rep++){
        int i  = tid + rep * 256;
        int rr = i >> 3;
        int cc = (i & 7) * 4;
        cp_async16(&a0[rr * SA_STRIDE + cc], &A[(size_t)(bm + rr) * 1024 + k0 + cc]);
    }
    #pragma unroll
    for (int rep = 0; rep < 4; rep++){
        int i  = tid + rep * 256;
        int kk = i >> 5;
        int cc = (i & 31) * 4;
        cp_async16(&b0[kk * SB_STRIDE + cc], &Bm[(size_t)(k0 + kk) * N + bn + cc]);
    }
    CP_COMMIT();
}

__device__ __forceinline__ void tf32_gemm_body(const unsigned* __restrict__ A,
                                               const unsigned* __restrict__ Bm,
                                               float* __restrict__ C,
                                               int N, float alpha)
{
    extern __shared__ unsigned smemu[];
    unsigned* sA = smemu;
    unsigned* sB = smemu + NSTAGE * SA_BUF;

    const int bm = blockIdx.y * 128;
    const int bn = blockIdx.x * 128;
    const int tid  = threadIdx.x;
    const int lane = tid & 31;
    const int wid  = tid >> 5;
    const int wm = (wid >> 2) * 64;
    const int wn = (wid & 3) * 32;
    const int g = lane >> 2;
    const int r = lane & 3;

    float acc[4][4][4];
    #pragma unroll
    for (int mt = 0; mt < 4; mt++)
        #pragma unroll
        for (int nt = 0; nt < 4; nt++)
            #pragma unroll
            for (int i = 0; i < 4; i++) acc[mt][nt][i] = 0.0f;

    const int NT = 1024 / 32;
    tf32_load_tiles(sA, sB, A, Bm, bm, bn, N, 0,  0, tid);
    tf32_load_tiles(sA, sB, A, Bm, bm, bn, N, 32, 1, tid);

    #pragma unroll 1
    for (int t = 0; t < NT; t++){
        if (t + 2 < NT){
            tf32_load_tiles(sA, sB, A, Bm, bm, bn, N, (t+2)*32, (t+2)%NSTAGE, tid);
            CP_WAIT(2);
        } else {
            CP_WAIT(0);
        }
        __syncthreads();

        const unsigned* a0 = sA + (t % NSTAGE) * SA_BUF;
        const unsigned* b0 = sB + (t % NSTAGE) * SB_BUF;

        #pragma unroll
        for (int ks = 0; ks < 32; ks += 8){
            unsigned af[4][4], bf[4][2];
            #pragma unroll
            for (int mt = 0; mt < 4; mt++){
                int row0 = wm + 16*mt + g;
                af[mt][0] = a0[ row0      * SA_STRIDE + ks + r    ];
                af[mt][1] = a0[(row0 + 8) * SA_STRIDE + ks + r    ];
                af[mt][2] = a0[ row0      * SA_STRIDE + ks + r + 4];
                af[mt][3] = a0[(row0 + 8) * SA_STRIDE + ks + r + 4];
            }
            #pragma unroll
            for (int nt = 0; nt < 4; nt++){
                int col = wn + 8*nt + g;
                bf[nt][0] = b0[(ks + r    ) * SB_STRIDE + col];
                bf[nt][1] = b0[(ks + r + 4) * SB_STRIDE + col];
            }
            #pragma unroll
            for (int mt = 0; mt < 4; mt++)
                #pragma unroll
                for (int nt = 0; nt < 4; nt++)
                    mma_tf32(acc[mt][nt], af[mt], bf[nt]);
        }
        __syncthreads();
    }

    #pragma unroll
    for (int mt = 0; mt < 4; mt++){
        int row = bm + wm + 16*mt + g;
        #pragma unroll
        for (int nt = 0; nt < 4; nt++){
            int col = bn + wn + 8*nt + 2*r;
            float2 v0 = make_float2(alpha*acc[mt][nt][0], alpha*acc[mt][nt][1]);
            float2 v1 = make_float2(alpha*acc[mt][nt][2], alpha*acc[mt][nt][3]);
            *(float2*)&C[(size_t)row       * N + col] = v0;
            *(float2*)&C[(size_t)(row + 8) * N + col] = v1;
        }
    }
}

__global__ void __launch_bounds__(256, 2)
tf32_proj_kernel(const unsigned* __restrict__ W, int sel, int N, float alpha)
{
    tf32_gemm_body(g_xC, W, proj_out(sel), N, alpha);
}

__global__ void __launch_bounds__(256, 2)
tf32_final_kernel(float* __restrict__ out)
{
    tf32_gemm_body((const unsigned*)g_bufZ, g_woC, out, Dsz, 1.0f);
}

// ---------------- t = x @ Wgk1  ([8192,1024] @ [1024,16]) ----------------------
__global__ void gemm_t_kernel(const float* __restrict__ x,
                              const float* __restrict__ W)
{
    __shared__ float sA[16][65];
    __shared__ float sB[16][17];
    const int bm = blockIdx.x * 64;
    const int tid = threadIdx.x;
    const int ty = tid >> 4, tx = tid & 15;
    float acc[4] = {};
    for (int k0 = 0; k0 < Dsz; k0 += 16){
        #pragma unroll
        for (int rep = 0; rep < 4; rep++){
            int i = tid + rep*256;
            int r = i >> 4, c = i & 15;
            sA[c][r] = x[(size_t)(bm + r) * Dsz + k0 + c];
        }
        {
            int r = tid >> 4, c = tid & 15;
            sB[r][c] = W[(size_t)(k0 + r) * RANKn + c];
        }
        __syncthreads();
        #pragma unroll
        for (int kk = 0; kk < 16; kk++){
            float b = sB[kk][tx];
            #pragma unroll
            for (int u = 0; u < 4; u++)
                acc[u] += sA[kk][ty*4+u] * b;
        }
        __syncthreads();
    }
    #pragma unroll
    for (int u = 0; u < 4; u++)
        g_bufT[(size_t)(bm + ty*4 + u) * RANKn + tx] = acc[u];
}

// ---------------- gk = log_sigmoid(t @ Wgk2 + bgk) / 16 -----------------------
__global__ void gk_kernel(const float* __restrict__ Wgk2,
                          const float* __restrict__ bgk)
{
    const int col = blockIdx.x * 256 + threadIdx.x;
    const int row = blockIdx.y;
    __shared__ float st[RANKn];
    if (threadIdx.x < RANKn) st[threadIdx.x] = g_bufT[(size_t)row * RANKn + threadIdx.x];
    __syncthreads();
    float acc = bgk[col];
    #pragma unroll
    for (int r = 0; r < RANKn; r++)
        acc += st[r] * Wgk2[r * KDn + col];
    float ls = fminf(acc, 0.0f) - log1pf(expf(-fabsf(acc)));
    g_bufGC[(size_t)row * KDn + col] = ls * (1.0f / 16.0f);
}

// ---------------- per-chunk cumsum of gk along time (in place) ----------------
__global__ void gcum_kernel()
{
    const int ch    = blockIdx.y * 256 + threadIdx.x;
    const int chunk = blockIdx.x;
    const int row0  = chunk * Csz;
    float s = 0.0f;
    for (int t = 0; t < Csz; t++){
        size_t idx = (size_t)(row0 + t) * KDn + ch;
        s += g_bufGC[idx];
        g_bufGC[idx] = s;
    }
}

// ---------------- intra-chunk A = tril( (q*e^g) @ (k*e^-g)^T ) -----------------
__global__ void attnA_kernel()
{
    const int chunk = blockIdx.x;
    const int h     = blockIdx.y;
    const int row0  = chunk * Csz;
    const int cb    = h * DKn;
    const int tid = threadIdx.x;
    const int ty = tid >> 4, tx = tid & 15;
    __shared__ float sq[16][65];
    __shared__ float sk[16][65];
    float acc[4][4] = {};
    for (int k0 = 0; k0 < DKn; k0 += 16){
        #pragma unroll
        for (int rep = 0; rep < 4; rep++){
            int i = tid + rep*256;
            int t = i >> 4, kk = i & 15;
            size_t idx = (size_t)(row0 + t) * KDn + cb + k0 + kk;
            float g = g_bufGC[idx];
            sq[kk][t] = g_bufQ[idx] * expf(g);
            sk[kk][t] = g_bufK[idx] * expf(-g);
        }
        __syncthreads();
        #pragma unroll
        for (int kk = 0; kk < 16; kk++){
            float a[4], b[4];
            #pragma unroll
            for (int u = 0; u < 4; u++){ a[u] = sq[kk][ty*4+u]; b[u] = sk[kk][tx*4+u]; }
            #pragma unroll
            for (int u = 0; u < 4; u++)
                #pragma unroll
                for (int w = 0; w < 4; w++)
                    acc[u][w] += a[u] * b[w];
        }
        __syncthreads();
    }
    #pragma unroll
    for (int u = 0; u < 4; u++)
        #pragma unroll
        for (int w = 0; w < 4; w++){
            int t = ty*4 + u, s = tx*4 + w;
            g_bufA[((size_t)(chunk*Hn + h) * Csz + t) * Csz + s] = (t >= s) ? acc[u][w] : 0.0f;
        }
}

// ---------------- per-chunk kv[k,v] = sum_s k_dec[s,k] * v[s,v] ----------------
__global__ void kv_kernel()
{
    const int chunk = blockIdx.x;
    const int h     = blockIdx.y;
    const int vb    = blockIdx.z;
    const int row0  = chunk * Csz;
    const int kc    = h * DKn;
    const int vc0   = h * DVn + vb * 64;
    const int n     = chunk & 63;
    const int bh    = (chunk >> 6) * Hn + h;
    const int tid = threadIdx.x;
    const int ty = tid >> 4, tx = tid & 15;

    __shared__ float skd[16][128];
    __shared__ float sv [16][65];
    __shared__ float gl [DKn];
    if (tid < DKn) gl[tid] = g_bufGC[(size_t)(row0 + Csz - 1) * KDn + kc + tid];
    __syncthreads();

    float acc[8][4] = {};
    for (int s0 = 0; s0 < Csz; s0 += 16){
        #pragma unroll
        for (int rep = 0; rep < 8; rep++){
            int i = tid + rep*256;
            int ss = i >> 7, kk = i & 127;
            size_t idx = (size_t)(row0 + s0 + ss) * KDn + kc + kk;
            skd[ss][kk] = g_bufK[idx] * expf(gl[kk] - g_bufGC[idx]);
        }
        #pragma unroll
        for (int rep = 0; rep < 4; rep++){
            int i = tid + rep*256;
            int ss = i >> 6, vv = i & 63;
            sv[ss][vv] = g_bufV[(size_t)(row0 + s0 + ss) * VDn + vc0 + vv];
        }
        __syncthreads();
        #pragma unroll
        for (int ss = 0; ss < 16; ss++){
            float a[8], b[4];
            #pragma unroll
            for (int u = 0; u < 8; u++) a[u] = skd[ss][ty*8+u];
            #pragma unroll
            for (int w = 0; w < 4; w++) b[w] = sv[ss][tx*4+w];
            #pragma unroll
            for (int u = 0; u < 8; u++)
                #pragma unroll
                for (int w = 0; w < 4; w++)
                    acc[u][w] += a[u] * b[w];
        }
        __syncthreads();
    }
    size_t base = ((size_t)(bh * NCn + n)) * DKn * DVn;
    #pragma unroll
    for (int u = 0; u < 8; u++)
        #pragma unroll
        for (int w = 0; w < 4; w++)
            g_bufKV[base + (size_t)(ty*8+u) * DVn + vb*64 + tx*4 + w] = acc[u][w];
}

// ---------------- inter-chunk scan (float4): S_0=0; S_{n+1}=S_n*e^{gl}+kv ------
__global__ void scan_kernel()
{
    const int bh    = blockIdx.x;
    const int elem4 = blockIdx.y * 256 + threadIdx.x;
    const int kk    = elem4 >> 6;
    const int b     = bh / Hn, h = bh % Hn;
    float4 s = make_float4(0.f, 0.f, 0.f, 0.f);
    for (int n = 0; n < NCn; n++){
        size_t base4 = ((size_t)(bh * NCn + n)) * (DKn * DVn / 4);
        ((float4*)g_bufS)[base4 + elem4] = s;
        float e = expf(g_bufGC[(size_t)((b * NCn + n) * Csz + Csz - 1) * KDn + h * DKn + kk]);
        float4 kv = ((const float4*)g_bufKV)[base4 + elem4];
        s.x = s.x * e + kv.x;
        s.y = s.y * e + kv.y;
        s.z = s.z * e + kv.z;
        s.w = s.w * e + kv.w;
    }
}

// ---------------- o = A @ v_chunk + q_t @ S_n ----------------------------------
__global__ void out_kernel()
{
    const int chunk = blockIdx.x;
    const int h     = blockIdx.y;
    const int vb    = blockIdx.z;
    const int row0  = chunk * Csz;
    const int n     = chunk & 63;
    const int bh    = (chunk >> 6) * Hn + h;
    const int vcol  = h * DVn + vb * 64;
    const int tid = threadIdx.x;
    const int ty = tid >> 4, tx = tid & 15;

    __shared__ float sa[16][65];
    __shared__ float sb[16][65];
    float acc[4][4] = {};

    for (int s0 = 0; s0 < Csz; s0 += 16){
        #pragma unroll
        for (int rep = 0; rep < 4; rep++){
            int i = tid + rep*256;
            int t = i >> 4, ss = i & 15;
            sa[ss][t] = g_bufA[((size_t)(chunk*Hn + h) * Csz + t) * Csz + s0 + ss];
        }
        #pragma unroll
        for (int rep = 0; rep < 4; rep++){
            int i = tid + rep*256;
            int ss = i >> 6, vv = i & 63;
            sb[ss][vv] = g_bufV[(size_t)(row0 + s0 + ss) * VDn + vcol + vv];
        }
        __syncthreads();
        #pragma unroll
        for (int ss = 0; ss < 16; ss++){
            float a[4], b[4];
            #pragma unroll
            for (int u = 0; u < 4; u++){ a[u] = sa[ss][ty*4+u]; b[u] = sb[ss][tx*4+u]; }
            #pragma unroll
            for (int u = 0; u < 4; u++)
                #pragma unroll
                for (int w = 0; w < 4; w++)
                    acc[u][w] += a[u] * b[w];
        }
        __syncthreads();
    }

    const size_t sbase = ((size_t)(bh * NCn + n)) * (DKn * DVn);
    for (int k0 = 0; k0 < DKn; k0 += 16){
        #pragma unroll
        for (int rep = 0; rep < 4; rep++){
            int i = tid + rep*256;
            int t = i >> 4, kk = i & 15;
            size_t idx = (size_t)(row0 + t) * KDn + h * DKn + k0 + kk;
            sa[kk][t] = g_bufQ[idx] * expf(g_bufGC[idx]);
        }
        #pragma unroll
        for (int rep = 0; rep < 4; rep++){
            int i = tid + rep*256;
            int kk = i >> 6, vv = i & 63;
            sb[kk][vv] = g_bufS[sbase + (size_t)(k0 + kk) * DVn + vb*64 + vv];
        }
        __syncthreads();
        #pragma unroll
        for (int kk = 0; kk < 16; kk++){
            float a[4], b[4];
            #pragma unroll
            for (int u = 0; u < 4; u++){ a[u] = sa[kk][ty*4+u]; b[u] = sb[kk][tx*4+u]; }
            #pragma unroll
            for (int u = 0; u < 4; u++)
                #pragma unroll
                for (int w = 0; w < 4; w++)
                    acc[u][w] += a[u] * b[w];
        }
        __syncthreads();
    }

    #pragma unroll
    for (int u = 0; u < 4; u++)
        #pragma unroll
        for (int w = 0; w < 4; w++)
            g_bufO[(size_t)(row0 + ty*4 + u) * VDn + vcol + tx*4 + w] = acc[u][w];
}

// ---------------- RMS-norm over DV + SiLU gate (norm_w shape (DV,)) ------------
// Writes tf32-rounded Z so the final GEMM can consume it directly.
__global__ void norm_gate_kernel(const float* __restrict__ norm_w)
{
    const int row = blockIdx.x;
    const int h   = blockIdx.y;
    const int tid = threadIdx.x;   // 256 == DVn
    size_t idx = (size_t)row * VDn + h * DVn + tid;
    float o = g_bufO[idx];
    float sq = o * o;
    #pragma unroll
    for (int off = 16; off; off >>= 1) sq += __shfl_xor_sync(0xffffffffu, sq, off);
    __shared__ float ws[8];
    if ((tid & 31) == 0) ws[tid >> 5] = sq;
    __syncthreads();
    float tot = 0.0f;
    #pragma unroll
    for (int i = 0; i < 8; i++) tot += ws[i];
    float r = rsqrtf(tot * (1.0f / 256.0f) + 1e-5f);
    float gv = g_bufG[idx];
    float silu = gv / (1.0f + expf(-gv));
    float z = o * r * norm_w[tid] * silu;
    g_bufZ[idx] = __uint_as_float(f2tf32(z));
}

// ---------------- launcher ------------------------------------------------------
extern "C" void kernel_launch(void* const* d_in, const int* in_sizes, int n_in,
                              void* d_out, int out_size)
{
    const float* x     = (const float*)d_in[0];
    const float* Wq    = (const float*)d_in[1];
    const float* Wk    = (const float*)d_in[2];
    const float* Wv    = (const float*)d_in[3];
    const float* Wgk1  = (const float*)d_in[4];
    const float* Wgk2  = (const float*)d_in[5];
    const float* bgk   = (const float*)d_in[6];
    const float* Wg    = (const float*)d_in[7];
    const float* Wo    = (const float*)d_in[8];
    const float* normw = (const float*)d_in[9];
    float* out = (float*)d_out;

    const float scale = 0.08838834764831845f;   // 1/sqrt(128)
    dim3 blk(256);
    const int smem_bytes = SMEM_WORDS * 4;      // ~107.5 KB

    cudaFuncSetAttribute(tf32_proj_kernel,
                         cudaFuncAttributeMaxDynamicSharedMemorySize, smem_bytes);
    cudaFuncSetAttribute(tf32_final_kernel,
                         cudaFuncAttributeMaxDynamicSharedMemorySize, smem_bytes);

    // pre-convert operands to tf32 bit patterns
    {
        unsigned *xc, *wqc, *wkc, *wvc, *wgc, *woc;
        cudaGetSymbolAddress((void**)&xc,  g_xC);
        cudaGetSymbolAddress((void**)&wqc, g_wqC);
        cudaGetSymbolAddress((void**)&wkc, g_wkC);
        cudaGetSymbolAddress((void**)&wvc, g_wvC);
        cudaGetSymbolAddress((void**)&wgc, g_wgC);
        cudaGetSymbolAddress((void**)&woc, g_woC);
        cvt_tf32_kernel<<<NROWS*Dsz/4/256, blk>>>(x,  xc,  NROWS*Dsz/4);
        cvt_tf32_kernel<<<Dsz*KDn/4/256,  blk>>>(Wq, wqc, Dsz*KDn/4);
        cvt_tf32_kernel<<<Dsz*KDn/4/256,  blk>>>(Wk, wkc, Dsz*KDn/4);
        cvt_tf32_kernel<<<Dsz*VDn/4/256,  blk>>>(Wv, wvc, Dsz*VDn/4);
        cvt_tf32_kernel<<<Dsz*VDn/4/256,  blk>>>(Wg, wgc, Dsz*VDn/4);
        cvt_tf32_kernel<<<VDn*Dsz/4/256,  blk>>>(Wo, woc, VDn*Dsz/4);
    }

    // projections on the tensor pipe (TF32, pre-converted, 3-stage cp.async)
    {
        unsigned *wqc, *wkc, *wvc, *wgc;
        cudaGetSymbolAddress((void**)&wqc, g_wqC);
        cudaGetSymbolAddress((void**)&wkc, g_wkC);
        cudaGetSymbolAddress((void**)&wvc, g_wvC);
        cudaGetSymbolAddress((void**)&wgc, g_wgC);
        tf32_proj_kernel<<<dim3(KDn/128, NROWS/128), blk, smem_bytes>>>(wqc, 0, KDn, scale);
        tf32_proj_kernel<<<dim3(KDn/128, NROWS/128), blk, smem_bytes>>>(wkc, 1, KDn, 1.0f);
        tf32_proj_kernel<<<dim3(VDn/128, NROWS/128), blk, smem_bytes>>>(wvc, 2, VDn, 1.0f);
        tf32_proj_kernel<<<dim3(VDn/128, NROWS/128), blk, smem_bytes>>>(wgc, 3, VDn, 1.0f);
    }

    // low-rank gate path (raw fp32 x for accuracy)
    gemm_t_kernel<<<NROWS/64, blk>>>(x, Wgk1);
    gk_kernel<<<dim3(KDn/256, NROWS), blk>>>(Wgk2, bgk);
    gcum_kernel<<<dim3(Bsz*NCn, KDn/256), blk>>>();

    // GLA chunks
    attnA_kernel<<<dim3(Bsz*NCn, Hn), blk>>>();
    kv_kernel<<<dim3(Bsz*NCn, Hn, DVn/64), blk>>>();
    scan_kernel<<<dim3(Bsz*Hn, (DKn*DVn)/4/256), blk>>>();
    out_kernel<<<dim3(Bsz*NCn, Hn, DVn/64), blk>>>();

    // epilogue
    norm_gate_kernel<<<dim3(NROWS, Hn), blk>>>(normw);
    tf32_final_kernel<<<dim3(Dsz/128, NROWS/128), blk, smem_bytes>>>(out);
}

// round 7
// speedup vs baseline: 1.0352x; 1.0352x over previous
#include <cuda_runtime.h>
#include <math.h>

// Problem constants
#define Bsz   2
#define Ssz   4096
#define Dsz   1024
#define Hn    4
#define DKn   128
#define DVn   256
#define KDn   512     // H*DK
#define VDn   1024    // H*DV
#define Csz   64
#define NCn   64      // S / C
#define RANKn 16
#define NROWS (Bsz*Ssz)   // 8192

// ---------------- scratch (device globals; no allocation allowed) -------------
__device__ float g_bufQ [NROWS*KDn];
__device__ float g_bufK [NROWS*KDn];
__device__ float g_bufV [NROWS*VDn];
__device__ float g_bufG [NROWS*VDn];
__device__ float g_bufGC[NROWS*KDn];
__device__ float g_bufT [NROWS*RANKn];
__device__ float g_bufA [Bsz*NCn*Hn*Csz*Csz];
__device__ float g_bufKV[Bsz*Hn*NCn*DKn*DVn];
__device__ float g_bufS [Bsz*Hn*NCn*DKn*DVn];
__device__ float g_bufO [NROWS*VDn];
__device__ float g_bufZ [NROWS*VDn];           // tf32-rounded at write time

// TF32 pre-converted operands
__device__ unsigned g_xC [NROWS*Dsz];
__device__ unsigned g_wqC[Dsz*KDn];
__device__ unsigned g_wkC[Dsz*KDn];
__device__ unsigned g_wvC[Dsz*VDn];
__device__ unsigned g_wgC[Dsz*VDn];
__device__ unsigned g_woC[VDn*Dsz];

__device__ __forceinline__ float* proj_out(int sel){
    switch(sel){
        case 0: return g_bufQ;
        case 1: return g_bufK;
        case 2: return g_bufV;
        default: return g_bufG;
    }
}

__device__ __forceinline__ unsigned f2tf32(float f){
    unsigned u;
    asm("cvt.rna.tf32.f32 %0, %1;" : "=r"(u) : "f"(f));
    return u;
}

// split v into tf32 hi + tf32 lo (3xTF32 decomposition)
__device__ __forceinline__ void split2(float v, float& h, float& l){
    float hh = __uint_as_float(f2tf32(v));
    h = hh;
    l = __uint_as_float(f2tf32(v - hh));
}

__device__ __forceinline__ unsigned fau(float f){ return __float_as_uint(f); }

// ---------------- elementwise fp32 -> tf32 conversion --------------------------
__global__ void cvt_tf32_kernel(const float* __restrict__ src,
                                unsigned* __restrict__ dst, int n4)
{
    int i = blockIdx.x * 256 + threadIdx.x;
    if (i < n4){
        float4 v = ((const float4*)src)[i];
        uint4 u;
        u.x = f2tf32(v.x); u.y = f2tf32(v.y); u.z = f2tf32(v.z); u.w = f2tf32(v.w);
        ((uint4*)dst)[i] = u;
    }
}

// ================= TF32 tensor-core GEMM (cp.async 3-stage) ====================
__device__ __forceinline__ void mma_tf32(float* d, const unsigned* a, const unsigned* b){
    asm volatile(
        "mma.sync.aligned.m16n8k8.row.col.f32.tf32.tf32.f32 "
        "{%0,%1,%2,%3}, {%4,%5,%6,%7}, {%8,%9}, {%0,%1,%2,%3};\n"
        : "+f"(d[0]), "+f"(d[1]), "+f"(d[2]), "+f"(d[3])
        : "r"(a[0]), "r"(a[1]), "r"(a[2]), "r"(a[3]), "r"(b[0]), "r"(b[1]));
}

__device__ __forceinline__ void cp_async16(void* smem_dst, const void* gmem_src){
    unsigned sa = (unsigned)__cvta_generic_to_shared(smem_dst);
    asm volatile("cp.async.cg.shared.global [%0], [%1], 16;\n" :: "r"(sa), "l"(gmem_src));
}
#define CP_COMMIT()  asm volatile("cp.async.commit_group;\n")
#define CP_WAIT(N)   asm volatile("cp.async.wait_group %0;\n" :: "n"(N))

#define SA_STRIDE 36
#define SB_STRIDE 136
#define SA_BUF    (128*SA_STRIDE)
#define SB_BUF    (32*SB_STRIDE)
#define NSTAGE    3
#define SMEM_WORDS (NSTAGE*(SA_BUF + SB_BUF))

__device__ __forceinline__ void tf32_load_tiles(unsigned* sA, unsigned* sB,
                                                const unsigned* __restrict__ A,
                                                const unsigned* __restrict__ Bm,
                                                int bm, int bn, int N, int k0, int buf,
                                                int tid)
{
    unsigned* a0 = sA + buf * SA_BUF;
    unsigned* b0 = sB + buf * SB_BUF;
    #pragma unroll
    for (int rep = 0; rep < 4; rep++){
        int i  = tid + rep * 256;
        int rr = i >> 3;
        int cc = (i & 7) * 4;
        cp_async16(&a0[rr * SA_STRIDE + cc], &A[(size_t)(bm + rr) * 1024 + k0 + cc]);
    }
    #pragma unroll
    for (int rep = 0; rep < 4; rep++){
        int i  = tid + rep * 256;
        int kk = i >> 5;
        int cc = (i & 31) * 4;
        cp_async16(&b0[kk * SB_STRIDE + cc], &Bm[(size_t)(k0 + kk) * N + bn + cc]);
    }
    CP_COMMIT();
}

__device__ __forceinline__ void tf32_gemm_body(const unsigned* __restrict__ A,
                                               const unsigned* __restrict__ Bm,
                                               float* __restrict__ C,
                                               int N, float alpha)
{
    extern __shared__ unsigned smemu[];
    unsigned* sA = smemu;
    unsigned* sB = smemu + NSTAGE * SA_BUF;

    const int bm = blockIdx.y * 128;
    const int bn = blockIdx.x * 128;
    const int tid  = threadIdx.x;
    const int lane = tid & 31;
    const int wid  = tid >> 5;
    const int wm = (wid >> 2) * 64;
    const int wn = (wid & 3) * 32;
    const int g = lane >> 2;
    const int r = lane & 3;

    float acc[4][4][4];
    #pragma unroll
    for (int mt = 0; mt < 4; mt++)
        #pragma unroll
        for (int nt = 0; nt < 4; nt++)
            #pragma unroll
            for (int i = 0; i < 4; i++) acc[mt][nt][i] = 0.0f;

    const int NT = 1024 / 32;
    tf32_load_tiles(sA, sB, A, Bm, bm, bn, N, 0,  0, tid);
    tf32_load_tiles(sA, sB, A, Bm, bm, bn, N, 32, 1, tid);

    #pragma unroll 1
    for (int t = 0; t < NT; t++){
        if (t + 2 < NT){
            tf32_load_tiles(sA, sB, A, Bm, bm, bn, N, (t+2)*32, (t+2)%NSTAGE, tid);
            CP_WAIT(2);
        } else {
            CP_WAIT(0);
        }
        __syncthreads();

        const unsigned* a0 = sA + (t % NSTAGE) * SA_BUF;
        const unsigned* b0 = sB + (t % NSTAGE) * SB_BUF;

        #pragma unroll
        for (int ks = 0; ks < 32; ks += 8){
            unsigned af[4][4], bf[4][2];
            #pragma unroll
            for (int mt = 0; mt < 4; mt++){
                int row0 = wm + 16*mt + g;
                af[mt][0] = a0[ row0      * SA_STRIDE + ks + r    ];
                af[mt][1] = a0[(row0 + 8) * SA_STRIDE + ks + r    ];
                af[mt][2] = a0[ row0      * SA_STRIDE + ks + r + 4];
                af[mt][3] = a0[(row0 + 8) * SA_STRIDE + ks + r + 4];
            }
            #pragma unroll
            for (int nt = 0; nt < 4; nt++){
                int col = wn + 8*nt + g;
                bf[nt][0] = b0[(ks + r    ) * SB_STRIDE + col];
                bf[nt][1] = b0[(ks + r + 4) * SB_STRIDE + col];
            }
            #pragma unroll
            for (int mt = 0; mt < 4; mt++)
                #pragma unroll
                for (int nt = 0; nt < 4; nt++)
                    mma_tf32(acc[mt][nt], af[mt], bf[nt]);
        }
        __syncthreads();
    }

    #pragma unroll
    for (int mt = 0; mt < 4; mt++){
        int row = bm + wm + 16*mt + g;
        #pragma unroll
        for (int nt = 0; nt < 4; nt++){
            int col = bn + wn + 8*nt + 2*r;
            float2 v0 = make_float2(alpha*acc[mt][nt][0], alpha*acc[mt][nt][1]);
            float2 v1 = make_float2(alpha*acc[mt][nt][2], alpha*acc[mt][nt][3]);
            *(float2*)&C[(size_t)row       * N + col] = v0;
            *(float2*)&C[(size_t)(row + 8) * N + col] = v1;
        }
    }
}

__global__ void __launch_bounds__(256, 2)
tf32_proj_kernel(const unsigned* __restrict__ W, int sel, int N, float alpha)
{
    tf32_gemm_body(g_xC, W, proj_out(sel), N, alpha);
}

__global__ void __launch_bounds__(256, 2)
tf32_final_kernel(float* __restrict__ out)
{
    tf32_gemm_body((const unsigned*)g_bufZ, g_woC, out, Dsz, 1.0f);
}

// ---------------- t = x @ Wgk1  ([8192,1024] @ [1024,16]) ----------------------
__global__ void gemm_t_kernel(const float* __restrict__ x,
                              const float* __restrict__ W)
{
    __shared__ float sA[16][65];
    __shared__ float sB[16][17];
    const int bm = blockIdx.x * 64;
    const int tid = threadIdx.x;
    const int ty = tid >> 4, tx = tid & 15;
    float acc[4] = {};
    for (int k0 = 0; k0 < Dsz; k0 += 16){
        #pragma unroll
        for (int rep = 0; rep < 4; rep++){
            int i = tid + rep*256;
            int r = i >> 4, c = i & 15;
            sA[c][r] = x[(size_t)(bm + r) * Dsz + k0 + c];
        }
        {
            int r = tid >> 4, c = tid & 15;
            sB[r][c] = W[(size_t)(k0 + r) * RANKn + c];
        }
        __syncthreads();
        #pragma unroll
        for (int kk = 0; kk < 16; kk++){
            float b = sB[kk][tx];
            #pragma unroll
            for (int u = 0; u < 4; u++)
                acc[u] += sA[kk][ty*4+u] * b;
        }
        __syncthreads();
    }
    #pragma unroll
    for (int u = 0; u < 4; u++)
        g_bufT[(size_t)(bm + ty*4 + u) * RANKn + tx] = acc[u];
}

// ---------------- gk = log_sigmoid(t @ Wgk2 + bgk) / 16 -----------------------
__global__ void gk_kernel(const float* __restrict__ Wgk2,
                          const float* __restrict__ bgk)
{
    const int col = blockIdx.x * 256 + threadIdx.x;
    const int row = blockIdx.y;
    __shared__ float st[RANKn];
    if (threadIdx.x < RANKn) st[threadIdx.x] = g_bufT[(size_t)row * RANKn + threadIdx.x];
    __syncthreads();
    float acc = bgk[col];
    #pragma unroll
    for (int r = 0; r < RANKn; r++)
        acc += st[r] * Wgk2[r * KDn + col];
    float ls = fminf(acc, 0.0f) - log1pf(expf(-fabsf(acc)));
    g_bufGC[(size_t)row * KDn + col] = ls * (1.0f / 16.0f);
}

// ---------------- per-chunk cumsum of gk along time (in place) ----------------
__global__ void gcum_kernel()
{
    const int ch    = blockIdx.y * 256 + threadIdx.x;
    const int chunk = blockIdx.x;
    const int row0  = chunk * Csz;
    float s = 0.0f;
    for (int t = 0; t < Csz; t++){
        size_t idx = (size_t)(row0 + t) * KDn + ch;
        s += g_bufGC[idx];
        g_bufGC[idx] = s;
    }
}

// ============ 3xTF32 MMA chunk kernels =========================================
// Shared padding rule: any SMEM row stride with stride % 32 == 4 (in floats)
// makes both A-fragment ((4g+r)%32 distinct) and B-fragment ((4r+g)%32 distinct)
// loads bank-conflict-free.

// ---------------- intra-chunk A = tril( (q*e^g) @ (k*e^-g)^T ), MMA ------------
// per (chunk,h): M=64(t), N=64(s), K=128. 8 warps in 4x2, warp tile 16x32.
__global__ void attnA_mma_kernel()
{
    const int chunk = blockIdx.x;
    const int h     = blockIdx.y;
    const int row0  = chunk * Csz;
    const int cb    = h * DKn;
    const int tid = threadIdx.x;
    const int lane = tid & 31;
    const int wid  = tid >> 5;
    const int wm = (wid >> 1) * 16;
    const int wn = (wid & 1) * 32;
    const int g = lane >> 2, r = lane & 3;

    __shared__ float sAh[64][20], sAl[64][20];   // q_t [t][kk]
    __shared__ float sBh[16][68], sBl[16][68];   // k_inv [kk][s]

    float acc[4][4];
    #pragma unroll
    for (int nt = 0; nt < 4; nt++)
        #pragma unroll
        for (int i = 0; i < 4; i++) acc[nt][i] = 0.0f;

    for (int k0 = 0; k0 < DKn; k0 += 16){
        // fill A (q_t): 64x16
        #pragma unroll
        for (int rep = 0; rep < 4; rep++){
            int i = tid + rep*256;
            int t = i >> 4, kk = i & 15;
            size_t idx = (size_t)(row0 + t) * KDn + cb + k0 + kk;
            float gg = g_bufGC[idx];
            float v = g_bufQ[idx] * expf(gg);
            split2(v, sAh[t][kk], sAl[t][kk]);
        }
        // fill B (k_inv, transposed): sB[kk][s]
        #pragma unroll
        for (int rep = 0; rep < 4; rep++){
            int i = tid + rep*256;
            int s = i >> 4, kk = i & 15;
            size_t idx = (size_t)(row0 + s) * KDn + cb + k0 + kk;
            float gg = g_bufGC[idx];
            float v = g_bufK[idx] * expf(-gg);
            split2(v, sBh[kk][s], sBl[kk][s]);
        }
        __syncthreads();

        #pragma unroll
        for (int ks = 0; ks < 16; ks += 8){
            unsigned ah[4], al[4];
            int rowa = wm + g;
            ah[0]=fau(sAh[rowa  ][ks+r  ]); ah[1]=fau(sAh[rowa+8][ks+r  ]);
            ah[2]=fau(sAh[rowa  ][ks+r+4]); ah[3]=fau(sAh[rowa+8][ks+r+4]);
            al[0]=fau(sAl[rowa  ][ks+r  ]); al[1]=fau(sAl[rowa+8][ks+r  ]);
            al[2]=fau(sAl[rowa  ][ks+r+4]); al[3]=fau(sAl[rowa+8][ks+r+4]);
            #pragma unroll
            for (int nt = 0; nt < 4; nt++){
                int col = wn + 8*nt + g;
                unsigned bh[2], bl[2];
                bh[0]=fau(sBh[ks+r  ][col]); bh[1]=fau(sBh[ks+r+4][col]);
                bl[0]=fau(sBl[ks+r  ][col]); bl[1]=fau(sBl[ks+r+4][col]);
                mma_tf32(acc[nt], ah, bh);
                mma_tf32(acc[nt], ah, bl);
                mma_tf32(acc[nt], al, bh);
            }
        }
        __syncthreads();
    }

    // epilogue with tril mask
    size_t abase = (size_t)(chunk*Hn + h) * Csz * Csz;
    int t0 = wm + g, t1 = wm + g + 8;
    #pragma unroll
    for (int nt = 0; nt < 4; nt++){
        int c0 = wn + 8*nt + 2*r;
        g_bufA[abase + (size_t)t0*Csz + c0    ] = (t0 >= c0    ) ? acc[nt][0] : 0.0f;
        g_bufA[abase + (size_t)t0*Csz + c0 + 1] = (t0 >= c0 + 1) ? acc[nt][1] : 0.0f;
        g_bufA[abase + (size_t)t1*Csz + c0    ] = (t1 >= c0    ) ? acc[nt][2] : 0.0f;
        g_bufA[abase + (size_t)t1*Csz + c0 + 1] = (t1 >= c0 + 1) ? acc[nt][3] : 0.0f;
    }
}

// ---------------- per-chunk kv = k_dec^T @ v, MMA ------------------------------
// per (chunk,h,vb): M=128(kk), N=128(vv), K=64(s). 8 warps 2x4, warp tile 64x32.
__global__ void kv_mma_kernel()
{
    const int chunk = blockIdx.x;
    const int h     = blockIdx.y;
    const int vb    = blockIdx.z;           // 0..1, 128 v-cols each
    const int row0  = chunk * Csz;
    const int cb    = h * DKn;
    const int vc0   = h * DVn + vb * 128;
    const int n     = chunk & 63;
    const int bh    = (chunk >> 6) * Hn + h;
    const int tid = threadIdx.x;
    const int lane = tid & 31;
    const int wid  = tid >> 5;
    const int wm = (wid >> 2) * 64;
    const int wn = (wid & 3) * 32;
    const int g = lane >> 2, r = lane & 3;

    __shared__ float sAh[128][20], sAl[128][20];   // k_dec [kk][ss]
    __shared__ float sBh[16][132], sBl[16][132];   // v [ss][vv]
    __shared__ float gl[DKn];
    if (tid < DKn) gl[tid] = g_bufGC[(size_t)(row0 + Csz - 1) * KDn + cb + tid];
    __syncthreads();

    float acc[4][4][4];
    #pragma unroll
    for (int mt = 0; mt < 4; mt++)
        #pragma unroll
        for (int nt = 0; nt < 4; nt++)
            #pragma unroll
            for (int i = 0; i < 4; i++) acc[mt][nt][i] = 0.0f;

    for (int s0 = 0; s0 < Csz; s0 += 16){
        // fill A (k_dec transposed): 128x16
        #pragma unroll
        for (int rep = 0; rep < 8; rep++){
            int i = tid + rep*256;
            int kk = i & 127, ss = i >> 7;
            size_t idx = (size_t)(row0 + s0 + ss) * KDn + cb + kk;
            float v = g_bufK[idx] * expf(gl[kk] - g_bufGC[idx]);
            split2(v, sAh[kk][ss], sAl[kk][ss]);
        }
        // fill B (v): 16x128
        #pragma unroll
        for (int rep = 0; rep < 2; rep++){
            int i = tid + rep*256;
            int ss = i >> 5, vv = (i & 31) * 4;
            float4 v4 = *(const float4*)&g_bufV[(size_t)(row0 + s0 + ss) * VDn + vc0 + vv];
            split2(v4.x, sBh[ss][vv  ], sBl[ss][vv  ]);
            split2(v4.y, sBh[ss][vv+1], sBl[ss][vv+1]);
            split2(v4.z, sBh[ss][vv+2], sBl[ss][vv+2]);
            split2(v4.w, sBh[ss][vv+3], sBl[ss][vv+3]);
        }
        __syncthreads();

        #pragma unroll
        for (int ks = 0; ks < 16; ks += 8){
            unsigned ah[4][4], al[4][4];
            #pragma unroll
            for (int mt = 0; mt < 4; mt++){
                int row = wm + 16*mt + g;
                ah[mt][0]=fau(sAh[row  ][ks+r  ]); ah[mt][1]=fau(sAh[row+8][ks+r  ]);
                ah[mt][2]=fau(sAh[row  ][ks+r+4]); ah[mt][3]=fau(sAh[row+8][ks+r+4]);
                al[mt][0]=fau(sAl[row  ][ks+r  ]); al[mt][1]=fau(sAl[row+8][ks+r  ]);
                al[mt][2]=fau(sAl[row  ][ks+r+4]); al[mt][3]=fau(sAl[row+8][ks+r+4]);
            }
            #pragma unroll
            for (int nt = 0; nt < 4; nt++){
                int col = wn + 8*nt + g;
                unsigned bh[2], bl[2];
                bh[0]=fau(sBh[ks+r  ][col]); bh[1]=fau(sBh[ks+r+4][col]);
                bl[0]=fau(sBl[ks+r  ][col]); bl[1]=fau(sBl[ks+r+4][col]);
                #pragma unroll
                for (int mt = 0; mt < 4; mt++){
                    mma_tf32(acc[mt][nt], ah[mt], bh);
                    mma_tf32(acc[mt][nt], ah[mt], bl);
                    mma_tf32(acc[mt][nt], al[mt], bh);
                }
            }
        }
        __syncthreads();
    }

    size_t base = ((size_t)(bh * NCn + n)) * DKn * DVn;
    #pragma unroll
    for (int mt = 0; mt < 4; mt++){
        int row = wm + 16*mt + g;
        #pragma unroll
        for (int nt = 0; nt < 4; nt++){
            int col = vb*128 + wn + 8*nt + 2*r;
            *(float2*)&g_bufKV[base + (size_t)row    *DVn + col] = make_float2(acc[mt][nt][0], acc[mt][nt][1]);
            *(float2*)&g_bufKV[base + (size_t)(row+8)*DVn + col] = make_float2(acc[mt][nt][2], acc[mt][nt][3]);
        }
    }
}

// ---------------- inter-chunk scan (float4) ------------------------------------
__global__ void scan_kernel()
{
    const int bh    = blockIdx.x;
    const int elem4 = blockIdx.y * 256 + threadIdx.x;
    const int kk    = elem4 >> 6;
    const int b     = bh / Hn, h = bh % Hn;
    float4 s = make_float4(0.f, 0.f, 0.f, 0.f);
    for (int n = 0; n < NCn; n++){
        size_t base4 = ((size_t)(bh * NCn + n)) * (DKn * DVn / 4);
        ((float4*)g_bufS)[base4 + elem4] = s;
        float e = expf(g_bufGC[(size_t)((b * NCn + n) * Csz + Csz - 1) * KDn + h * DKn + kk]);
        float4 kv = ((const float4*)g_bufKV)[base4 + elem4];
        s.x = s.x * e + kv.x;
        s.y = s.y * e + kv.y;
        s.z = s.z * e + kv.z;
        s.w = s.w * e + kv.w;
    }
}

// ---------------- o = A @ v + q_t @ S, MMA -------------------------------------
// per (chunk,h): M=64(t), N=256(vv). 8 warps 1x8, warp tile 64x32 (mt=4, nt=4).
__global__ void out_mma_kernel()
{
    const int chunk = blockIdx.x;
    const int h     = blockIdx.y;
    const int row0  = chunk * Csz;
    const int cb    = h * DKn;
    const int vc0   = h * DVn;
    const int n     = chunk & 63;
    const int bh    = (chunk >> 6) * Hn + h;
    const int tid = threadIdx.x;
    const int lane = tid & 31;
    const int wid  = tid >> 5;
    const int wn = wid * 32;
    const int g = lane >> 2, r = lane & 3;

    __shared__ float sAh[64][20], sAl[64][20];    // A-operand [t][k]
    __shared__ float sBh[16][260], sBl[16][260];  // B-operand [k][vv]

    float acc[4][4][4];
    #pragma unroll
    for (int mt = 0; mt < 4; mt++)
        #pragma unroll
        for (int nt = 0; nt < 4; nt++)
            #pragma unroll
            for (int i = 0; i < 4; i++) acc[mt][nt][i] = 0.0f;

    const size_t abase = (size_t)(chunk*Hn + h) * Csz * Csz;
    const size_t sbase = ((size_t)(bh * NCn + n)) * (DKn * DVn);

    // ---- phase 1: A(masked) @ v, K = 64 ----
    for (int k0 = 0; k0 < Csz; k0 += 16){
        #pragma unroll
        for (int rep = 0; rep < 4; rep++){
            int i = tid + rep*256;
            int t = i >> 4, kk = i & 15;
            float v = g_bufA[abase + (size_t)t*Csz + k0 + kk];
            split2(v, sAh[t][kk], sAl[t][kk]);
        }
        #pragma unroll
        for (int rep = 0; rep < 4; rep++){
            int i = tid + rep*256;
            int ss = i >> 6, vv = (i & 63) * 4;
            float4 v4 = *(const float4*)&g_bufV[(size_t)(row0 + k0 + ss) * VDn + vc0 + vv];
            split2(v4.x, sBh[ss][vv  ], sBl[ss][vv  ]);
            split2(v4.y, sBh[ss][vv+1], sBl[ss][vv+1]);
            split2(v4.z, sBh[ss][vv+2], sBl[ss][vv+2]);
            split2(v4.w, sBh[ss][vv+3], sBl[ss][vv+3]);
        }
        __syncthreads();
        #pragma unroll
        for (int ks = 0; ks < 16; ks += 8){
            unsigned ah[4][4], al[4][4];
            #pragma unroll
            for (int mt = 0; mt < 4; mt++){
                int row = 16*mt + g;
                ah[mt][0]=fau(sAh[row  ][ks+r  ]); ah[mt][1]=fau(sAh[row+8][ks+r  ]);
                ah[mt][2]=fau(sAh[row  ][ks+r+4]); ah[mt][3]=fau(sAh[row+8][ks+r+4]);
                al[mt][0]=fau(sAl[row  ][ks+r  ]); al[mt][1]=fau(sAl[row+8][ks+r  ]);
                al[mt][2]=fau(sAl[row  ][ks+r+4]); al[mt][3]=fau(sAl[row+8][ks+r+4]);
            }
            #pragma unroll
            for (int nt = 0; nt < 4; nt++){
                int col = wn + 8*nt + g;
                unsigned bh[2], bl[2];
                bh[0]=fau(sBh[ks+r  ][col]); bh[1]=fau(sBh[ks+r+4][col]);
                bl[0]=fau(sBl[ks+r  ][col]); bl[1]=fau(sBl[ks+r+4][col]);
                #pragma unroll
                for (int mt = 0; mt < 4; mt++){
                    mma_tf32(acc[mt][nt], ah[mt], bh);
                    mma_tf32(acc[mt][nt], ah[mt], bl);
                    mma_tf32(acc[mt][nt], al[mt], bh);
                }
            }
        }
        __syncthreads();
    }

    // ---- phase 2: q_t @ S, K = 128 ----
    for (int k0 = 0; k0 < DKn; k0 += 16){
        #pragma unroll
        for (int rep = 0; rep < 4; rep++){
            int i = tid + rep*256;
            int t = i >> 4, kk = i & 15;
            size_t idx = (size_t)(row0 + t) * KDn + cb + k0 + kk;
            float v = g_bufQ[idx] * expf(g_bufGC[idx]);
            split2(v, sAh[t][kk], sAl[t][kk]);
        }
        #pragma unroll
        for (int rep = 0; rep < 4; rep++){
            int i = tid + rep*256;
            int kk = i >> 6, vv = (i & 63) * 4;
            float4 v4 = *(const float4*)&g_bufS[sbase + (size_t)(k0 + kk) * DVn + vv];
            split2(v4.x, sBh[kk][vv  ], sBl[kk][vv  ]);
            split2(v4.y, sBh[kk][vv+1], sBl[kk][vv+1]);
            split2(v4.z, sBh[kk][vv+2], sBl[kk][vv+2]);
            split2(v4.w, sBh[kk][vv+3], sBl[kk][vv+3]);
        }
        __syncthreads();
        #pragma unroll
        for (int ks = 0; ks < 16; ks += 8){
            unsigned ah[4][4], al[4][4];
            #pragma unroll
            for (int mt = 0; mt < 4; mt++){
                int row = 16*mt + g;
                ah[mt][0]=fau(sAh[row  ][ks+r  ]); ah[mt][1]=fau(sAh[row+8][ks+r  ]);
                ah[mt][2]=fau(sAh[row  ][ks+r+4]); ah[mt][3]=fau(sAh[row+8][ks+r+4]);
                al[mt][0]=fau(sAl[row  ][ks+r  ]); al[mt][1]=fau(sAl[row+8][ks+r  ]);
                al[mt][2]=fau(sAl[row  ][ks+r+4]); al[mt][3]=fau(sAl[row+8][ks+r+4]);
            }
            #pragma unroll
            for (int nt = 0; nt < 4; nt++){
                int col = wn + 8*nt + g;
                unsigned bh[2], bl[2];
                bh[0]=fau(sBh[ks+r  ][col]); bh[1]=fau(sBh[ks+r+4][col]);
                bl[0]=fau(sBl[ks+r  ][col]); bl[1]=fau(sBl[ks+r+4][col]);
                #pragma unroll
                for (int mt = 0; mt < 4; mt++){
                    mma_tf32(acc[mt][nt], ah[mt], bh);
                    mma_tf32(acc[mt][nt], ah[mt], bl);
                    mma_tf32(acc[mt][nt], al[mt], bh);
                }
            }
        }
        __syncthreads();
    }

    #pragma unroll
    for (int mt = 0; mt < 4; mt++){
        int row = row0 + 16*mt + g;
        #pragma unroll
        for (int nt = 0; nt < 4; nt++){
            int col = vc0 + wn + 8*nt + 2*r;
            *(float2*)&g_bufO[(size_t)row    *VDn + col] = make_float2(acc[mt][nt][0], acc[mt][nt][1]);
            *(float2*)&g_bufO[(size_t)(row+8)*VDn + col] = make_float2(acc[mt][nt][2], acc[mt][nt][3]);
        }
    }
}

// ---------------- RMS-norm over DV + SiLU gate (norm_w shape (DV,)) ------------
__global__ void norm_gate_kernel(const float* __restrict__ norm_w)
{
    const int row = blockIdx.x;
    const int h   = blockIdx.y;
    const int tid = threadIdx.x;   // 256 == DVn
    size_t idx = (size_t)row * VDn + h * DVn + tid;
    float o = g_bufO[idx];
    float sq = o * o;
    #pragma unroll
    for (int off = 16; off; off >>= 1) sq += __shfl_xor_sync(0xffffffffu, sq, off);
    __shared__ float ws[8];
    if ((tid & 31) == 0) ws[tid >> 5] = sq;
    __syncthreads();
    float tot = 0.0f;
    #pragma unroll
    for (int i = 0; i < 8; i++) tot += ws[i];
    float r = rsqrtf(tot * (1.0f / 256.0f) + 1e-5f);
    float gv = g_bufG[idx];
    float silu = gv / (1.0f + expf(-gv));
    float z = o * r * norm_w[tid] * silu;
    g_bufZ[idx] = __uint_as_float(f2tf32(z));
}

// ---------------- launcher ------------------------------------------------------
extern "C" void kernel_launch(void* const* d_in, const int* in_sizes, int n_in,
                              void* d_out, int out_size)
{
    const float* x     = (const float*)d_in[0];
    const float* Wq    = (const float*)d_in[1];
    const float* Wk    = (const float*)d_in[2];
    const float* Wv    = (const float*)d_in[3];
    const float* Wgk1  = (const float*)d_in[4];
    const float* Wgk2  = (const float*)d_in[5];
    const float* bgk   = (const float*)d_in[6];
    const float* Wg    = (const float*)d_in[7];
    const float* Wo    = (const float*)d_in[8];
    const float* normw = (const float*)d_in[9];
    float* out = (float*)d_out;

    const float scale = 0.08838834764831845f;   // 1/sqrt(128)
    dim3 blk(256);
    const int smem_bytes = SMEM_WORDS * 4;

    cudaFuncSetAttribute(tf32_proj_kernel,
                         cudaFuncAttributeMaxDynamicSharedMemorySize, smem_bytes);
    cudaFuncSetAttribute(tf32_final_kernel,
                         cudaFuncAttributeMaxDynamicSharedMemorySize, smem_bytes);

    // pre-convert operands to tf32 bit patterns
    {
        unsigned *xc, *wqc, *wkc, *wvc, *wgc, *woc;
        cudaGetSymbolAddress((void**)&xc,  g_xC);
        cudaGetSymbolAddress((void**)&wqc, g_wqC);
        cudaGetSymbolAddress((void**)&wkc, g_wkC);
        cudaGetSymbolAddress((void**)&wvc, g_wvC);
        cudaGetSymbolAddress((void**)&wgc, g_wgC);
        cudaGetSymbolAddress((void**)&woc, g_woC);
        cvt_tf32_kernel<<<NROWS*Dsz/4/256, blk>>>(x,  xc,  NROWS*Dsz/4);
        cvt_tf32_kernel<<<Dsz*KDn/4/256,  blk>>>(Wq, wqc, Dsz*KDn/4);
        cvt_tf32_kernel<<<Dsz*KDn/4/256,  blk>>>(Wk, wkc, Dsz*KDn/4);
        cvt_tf32_kernel<<<Dsz*VDn/4/256,  blk>>>(Wv, wvc, Dsz*VDn/4);
        cvt_tf32_kernel<<<Dsz*VDn/4/256,  blk>>>(Wg, wgc, Dsz*VDn/4);
        cvt_tf32_kernel<<<VDn*Dsz/4/256,  blk>>>(Wo, woc, VDn*Dsz/4);
    }

    // projections on the tensor pipe (TF32)
    {
        unsigned *wqc, *wkc, *wvc, *wgc;
        cudaGetSymbolAddress((void**)&wqc, g_wqC);
        cudaGetSymbolAddress((void**)&wkc, g_wkC);
        cudaGetSymbolAddress((void**)&wvc, g_wvC);
        cudaGetSymbolAddress((void**)&wgc, g_wgC);
        tf32_proj_kernel<<<dim3(KDn/128, NROWS/128), blk, smem_bytes>>>(wqc, 0, KDn, scale);
        tf32_proj_kernel<<<dim3(KDn/128, NROWS/128), blk, smem_bytes>>>(wkc, 1, KDn, 1.0f);
        tf32_proj_kernel<<<dim3(VDn/128, NROWS/128), blk, smem_bytes>>>(wvc, 2, VDn, 1.0f);
        tf32_proj_kernel<<<dim3(VDn/128, NROWS/128), blk, smem_bytes>>>(wgc, 3, VDn, 1.0f);
    }

    // low-rank gate path (raw fp32 x for accuracy)
    gemm_t_kernel<<<NROWS/64, blk>>>(x, Wgk1);
    gk_kernel<<<dim3(KDn/256, NROWS), blk>>>(Wgk2, bgk);
    gcum_kernel<<<dim3(Bsz*NCn, KDn/256), blk>>>();

    // GLA chunks — 3xTF32 MMA
    attnA_mma_kernel<<<dim3(Bsz*NCn, Hn), blk>>>();
    kv_mma_kernel<<<dim3(Bsz*NCn, Hn, 2), blk>>>();
    scan_kernel<<<dim3(Bsz*Hn, (DKn*DVn)/4/256), blk>>>();
    out_mma_kernel<<<dim3(Bsz*NCn, Hn), blk>>>();

    // epilogue
    norm_gate_kernel<<<dim3(NROWS, Hn), blk>>>(normw);
    tf32_final_kernel<<<dim3(Dsz/128, NROWS/128), blk, smem_bytes>>>(out);
}